// round 12
// baseline (speedup 1.0000x reference)
#include <cuda_runtime.h>
#include <math.h>

#define NBATCH 8
#define NPTS   256
#define NRBF_  50
#define NK     255
#define SD     8960

__device__ float g_vx[NBATCH * NPTS * 3];
__device__ float g_tr[NBATCH * NPTS];

typedef unsigned long long u64;

__device__ __forceinline__ u64 pack2(float x, float y) {
  u64 r; asm("mov.b64 %0,{%1,%2};" : "=l"(r) : "f"(x), "f"(y)); return r;
}
__device__ __forceinline__ float2 unpack2(u64 v) {
  float2 f; asm("mov.b64 {%0,%1},%2;" : "=f"(f.x), "=f"(f.y) : "l"(v)); return f;
}
__device__ __forceinline__ u64 ffma2(u64 a, u64 b, u64 c) {
  u64 d; asm("fma.rn.f32x2 %0,%1,%2,%3;" : "=l"(d) : "l"(a), "l"(b), "l"(c)); return d;
}
__device__ __forceinline__ float sgm(float z) {  // sigmoid via tanh (1 MUFU)
  float t; asm("tanh.approx.f32 %0, %1;" : "=f"(t) : "f"(0.5f * z));
  return fmaf(0.5f, t, 0.5f);
}

// ---- shared memory layout (floats) ----
#define O_W1   0
#define O_WM   (O_W1 + 6400)
#define O_W2   (O_WM + 6400)
#define O_WF   (O_W2 + 6400)
#define O_V21  (O_WF + 6400)
#define O_V22  (O_V21 + 128)
#define O_CF1  (O_V22 + 128)
#define O_CF2  (O_CF1 + 128)
#define O_CFF  (O_CF2 + 128)
#define O_XS   (O_CFF + 128)
#define O_FS   (O_XS + 768)
#define O_SMX  (O_FS + 32)
#define O_MUS  (O_SMX + 32)
#define O_HS   (O_MUS + 64)
#define O_HT   (O_HS + 512)
#define O_RED  (O_HT + 128)
#define O_TOT  (O_RED + 32)
#define O_DD   (O_TOT + 8)          // 256 distances
#define O_SK   (O_DD + 256)         // 256 sorted original-k indices (as int)
#define SMEM_FLOATS (O_SK + 256)    // 28328 floats = 113312 B

#define EPI(A11, AM1, A21, AF1, A12, AM2, A22, AF2, C1, C2, CF, W21, W22, HIDX) do { \
    float z1a = (A11) + (C1);                                                 \
    float sga = sgm(z1a);                                                     \
    s1a1 = fmaf(z1a * sga, (W21), s1a1);                                      \
    float spa = sga * fmaf(z1a, 1.f - sga, 1.f);                              \
    da1 = fmaf((W21) * spa, fmaf(d1, (A11), -(AM1)), da1);                    \
    float z1b = (A12) + (C1);                                                 \
    float sgb = sgm(z1b);                                                     \
    s1a2 = fmaf(z1b * sgb, (W21), s1a2);                                      \
    float spb = sgb * fmaf(z1b, 1.f - sgb, 1.f);                              \
    da2 = fmaf((W21) * spb, fmaf(d2, (A12), -(AM2)), da2);                    \
    float z2a = (A21) + (C2);                                                 \
    s2a1 = fmaf(z2a * sgm(z2a), (W22), s2a1);                                 \
    float z2b = (A22) + (C2);                                                 \
    s2a2 = fmaf(z2b * sgm(z2b), (W22), s2a2);                                 \
    float zfa = (AF1) + (CF);                                                 \
    float zfb = (AF2) + (CF);                                                 \
    float slf = fmaf(zfb * sgm(zfb), act2, zfa * sgm(zfa));                   \
    _Pragma("unroll")                                                         \
    for (int o = 16; o; o >>= 1) slf += __shfl_xor_sync(0xffffffffu, slf, o); \
    if (lane == 0) smf[O_HS + wid * 128 + (HIDX)] += slf;                     \
  } while (0)

__global__ __launch_bounds__(128, 2) void fd_main(
    const float* __restrict__ state, const float* __restrict__ mus,
    const float* __restrict__ gamma_p,
    const float* __restrict__ s1W1, const float* __restrict__ s1b1,
    const float* __restrict__ s1W2, const float* __restrict__ s1b2,
    const float* __restrict__ s2W1, const float* __restrict__ s2b1,
    const float* __restrict__ s2W2, const float* __restrict__ s2b2,
    const float* __restrict__ fW1, const float* __restrict__ fb1,
    const float* __restrict__ fW2, const float* __restrict__ fb2,
    float* __restrict__ out)
{
  extern __shared__ float smf[];
  int* smi = (int*)smf;
  const int tid = threadIdx.x;
  const int wid = tid >> 5, lane = tid & 31;
  const int bi = blockIdx.x;
  const int b = bi >> 8;
  const int i = bi & 255;
  const float gam = gamma_p[0];

  // --- stage weights / inputs ---
  for (int idx = tid; idx < 6400; idx += 128) {
    float w = s1W1[idx];
    smf[O_W1 + idx] = w;
    smf[O_WM + idx] = w * mus[idx >> 7];
    smf[O_W2 + idx] = s2W1[idx];
    smf[O_WF + idx] = fW1[idx];
  }
  smf[O_V21 + tid] = s1W2[tid];
  smf[O_V22 + tid] = s2W2[tid];
  for (int idx = tid; idx < 512; idx += 128) smf[O_HS + idx] = 0.f;
  for (int idx = tid; idx < 768; idx += 128) smf[O_XS + idx] = state[b * SD + idx];
  if (tid < 32) smf[O_FS + tid] = state[b * SD + 768 + i * 32 + tid];
  if (tid < 64) smf[O_MUS + tid] = (tid < NRBF_) ? mus[tid] : 0.f;
  __syncthreads();

  // --- distances for all neighbors (k = tid and k = tid+128) ---
  const float xi0 = smf[O_XS + i * 3 + 0];
  const float xi1 = smf[O_XS + i * 3 + 1];
  const float xi2 = smf[O_XS + i * 3 + 2];
  {
    int k = tid;
    int j = (k < i) ? k : k + 1;
    float dx = xi0 - smf[O_XS + j * 3 + 0];
    float dy = xi1 - smf[O_XS + j * 3 + 1];
    float dz = xi2 - smf[O_XS + j * 3 + 2];
    smf[O_DD + k] = sqrtf(dx * dx + dy * dy + dz * dz + 1e-6f);
    int k2s = tid + 128;
    if (k2s < NK) {
      int j2 = (k2s < i) ? k2s : k2s + 1;
      float ex = xi0 - smf[O_XS + j2 * 3 + 0];
      float ey = xi1 - smf[O_XS + j2 * 3 + 1];
      float ez = xi2 - smf[O_XS + j2 * 3 + 2];
      smf[O_DD + k2s] = sqrtf(ex * ex + ey * ey + ez * ez + 1e-6f);
    } else {
      smf[O_DD + 255] = 1e30f;   // sentinel sorts last
    }
  }
  // softmax(feats) by warp 0
  if (tid < 32) {
    float v = smf[O_FS + tid];
    float mx = v;
    #pragma unroll
    for (int o = 16; o; o >>= 1) mx = fmaxf(mx, __shfl_xor_sync(0xffffffffu, mx, o));
    float e = __expf(v - mx);
    float s = e;
    #pragma unroll
    for (int o = 16; o; o >>= 1) s += __shfl_xor_sync(0xffffffffu, s, o);
    smf[O_SMX + tid] = __fdividef(e, s);
  }
  __syncthreads();

  // --- rank-sort both owned entries by (d, index) ---
  {
    const int ka = tid, kb = tid + 128;
    const float va = smf[O_DD + ka], vb = smf[O_DD + kb];
    int ra = 0, rb = 0;
    #pragma unroll 4
    for (int j = 0; j < 256; j++) {
      float v = smf[O_DD + j];
      ra += (v < va) || (v == va && j < ka);
      rb += (v < vb) || (v == vb && j < kb);
    }
    smi[O_SK + ra] = ka;
    smi[O_SK + rb] = kb;
  }
  // per-(b,i) constant hidden contributions
  {
    const int h = tid;
    float c1 = s1b1[h], c2 = s2b1[h], cf = fb1[h];
    #pragma unroll 4
    for (int f = 0; f < 32; f++) {
      float fv = smf[O_FS + f];
      c1 = fmaf(fv, s1W1[(50 + f) * 128 + h] + s1W1[(82 + f) * 128 + h], c1);
      c2 = fmaf(fv, s2W1[(50 + f) * 128 + h] + s2W1[(82 + f) * 128 + h], c2);
      cf = fmaf(smf[O_SMX + f], fW1[(50 + f) * 128 + h], cf);
    }
    smf[O_CF1 + h] = c1;
    smf[O_CF2 + h] = c2;
    smf[O_CFF + h] = cf;
  }
  __syncthreads();

  // --- this thread's 2 sorted neighbors ---
  const int k1 = smi[O_SK + 2 * tid];
  const int k2r = smi[O_SK + 2 * tid + 1];
  const float act2 = (k2r < NK) ? 1.f : 0.f;
  const int k2 = (k2r < NK) ? k2r : k1;
  const int j1 = (k1 < i) ? k1 : k1 + 1;
  const int j2 = (k2 < i) ? k2 : k2 + 1;
  const float rx1 = xi0 - smf[O_XS + j1 * 3 + 0];
  const float ry1 = xi1 - smf[O_XS + j1 * 3 + 1];
  const float rz1 = xi2 - smf[O_XS + j1 * 3 + 2];
  const float rx2 = xi0 - smf[O_XS + j2 * 3 + 0];
  const float ry2 = xi1 - smf[O_XS + j2 * 3 + 1];
  const float rz2 = xi2 - smf[O_XS + j2 * 3 + 2];
  const float rr1 = rx1 * rx1 + ry1 * ry1 + rz1 * rz1;
  const float rr2q = rx2 * rx2 + ry2 * ry2 + rz2 * rz2;
  const float d1 = sqrtf(rr1 + 1e-6f);
  const float d2 = sqrtf(rr2q + 1e-6f);

  // --- warp-uniform RBF window from warp d-range ---
  float dmn = fminf(d1, d2), dmx = fmaxf(d1, d2);
  #pragma unroll
  for (int o = 16; o; o >>= 1) {
    dmn = fminf(dmn, __shfl_xor_sync(0xffffffffu, dmn, o));
    dmx = fmaxf(dmx, __shfl_xor_sync(0xffffffffu, dmx, o));
  }
  const float MU_STEP = 5.0f / 49.0f;
  const float RCUT = 1.02f;
  int m_lo = (int)floorf((dmn - RCUT) / MU_STEP) - 1;
  int m_hi = (int)ceilf((dmx + RCUT) / MU_STEP) + 1;
  m_lo = max(0, min(49, m_lo));
  m_hi = max(m_lo, min(49, m_hi));
  const int nm = m_hi - m_lo + 1;
  const int n1 = min(nm, 32), n2 = nm - n1;

  // --- rbf prologue (fixed-size, constant-indexed arrays) ---
  float r1a[32], r2a[32], r1b[18], r2b[18];
  #pragma unroll
  for (int mi = 0; mi < 32; mi++) {
    int m = m_lo + mi; int mc = m > 49 ? 49 : m;
    float mu = smf[O_MUS + mc];
    float t1 = d1 - mu, t2 = d2 - mu;
    float v1 = __expf(-gam * t1 * t1), v2 = __expf(-gam * t2 * t2);
    bool on = (mi < n1);
    r1a[mi] = on ? v1 : 0.f;
    r2a[mi] = on ? v2 : 0.f;
  }
  if (n2 > 0) {
    #pragma unroll
    for (int mi = 0; mi < 18; mi++) {
      int m = m_lo + 32 + mi; int mc = m > 49 ? 49 : m;
      float mu = smf[O_MUS + mc];
      float t1 = d1 - mu, t2 = d2 - mu;
      float v1 = __expf(-gam * t1 * t1), v2 = __expf(-gam * t2 * t2);
      bool on = (mi < n2);
      r1b[mi] = on ? v1 : 0.f;
      r2b[mi] = on ? v2 : 0.f;
    }
  }

  float s1a1 = 0.f, s1a2 = 0.f, s2a1 = 0.f, s2a2 = 0.f, da1 = 0.f, da2 = 0.f;

  #pragma unroll 1
  for (int hb = 0; hb < 128; hb += 4) {
    u64 A1a1 = 0ull, A1b1 = 0ull, A1a2 = 0ull, A1b2 = 0ull;
    u64 AMa1 = 0ull, AMb1 = 0ull, AMa2 = 0ull, AMb2 = 0ull;
    u64 A2a1 = 0ull, A2b1 = 0ull, A2a2 = 0ull, A2b2 = 0ull;
    u64 AFa1 = 0ull, AFb1 = 0ull, AFa2 = 0ull, AFb2 = 0ull;
    #pragma unroll
    for (int mi = 0; mi < 32; mi++) {
      if (mi >= n1) break;
      const int m = m_lo + mi;
      const u64 rv1 = pack2(r1a[mi], r1a[mi]);
      const u64 rv2 = pack2(r2a[mi], r2a[mi]);
      const ulonglong2 w1 = *reinterpret_cast<const ulonglong2*>(&smf[O_W1 + m * 128 + hb]);
      A1a1 = ffma2(rv1, w1.x, A1a1);  A1b1 = ffma2(rv1, w1.y, A1b1);
      A1a2 = ffma2(rv2, w1.x, A1a2);  A1b2 = ffma2(rv2, w1.y, A1b2);
      const ulonglong2 wm = *reinterpret_cast<const ulonglong2*>(&smf[O_WM + m * 128 + hb]);
      AMa1 = ffma2(rv1, wm.x, AMa1);  AMb1 = ffma2(rv1, wm.y, AMb1);
      AMa2 = ffma2(rv2, wm.x, AMa2);  AMb2 = ffma2(rv2, wm.y, AMb2);
      const ulonglong2 w2 = *reinterpret_cast<const ulonglong2*>(&smf[O_W2 + m * 128 + hb]);
      A2a1 = ffma2(rv1, w2.x, A2a1);  A2b1 = ffma2(rv1, w2.y, A2b1);
      A2a2 = ffma2(rv2, w2.x, A2a2);  A2b2 = ffma2(rv2, w2.y, A2b2);
      const ulonglong2 wf = *reinterpret_cast<const ulonglong2*>(&smf[O_WF + m * 128 + hb]);
      AFa1 = ffma2(rv1, wf.x, AFa1);  AFb1 = ffma2(rv1, wf.y, AFb1);
      AFa2 = ffma2(rv2, wf.x, AFa2);  AFb2 = ffma2(rv2, wf.y, AFb2);
    }
    if (n2 > 0) {
      #pragma unroll
      for (int mi = 0; mi < 18; mi++) {
        if (mi >= n2) break;
        const int m = m_lo + 32 + mi;
        const u64 rv1 = pack2(r1b[mi], r1b[mi]);
        const u64 rv2 = pack2(r2b[mi], r2b[mi]);
        const ulonglong2 w1 = *reinterpret_cast<const ulonglong2*>(&smf[O_W1 + m * 128 + hb]);
        A1a1 = ffma2(rv1, w1.x, A1a1);  A1b1 = ffma2(rv1, w1.y, A1b1);
        A1a2 = ffma2(rv2, w1.x, A1a2);  A1b2 = ffma2(rv2, w1.y, A1b2);
        const ulonglong2 wm = *reinterpret_cast<const ulonglong2*>(&smf[O_WM + m * 128 + hb]);
        AMa1 = ffma2(rv1, wm.x, AMa1);  AMb1 = ffma2(rv1, wm.y, AMb1);
        AMa2 = ffma2(rv2, wm.x, AMa2);  AMb2 = ffma2(rv2, wm.y, AMb2);
        const ulonglong2 w2 = *reinterpret_cast<const ulonglong2*>(&smf[O_W2 + m * 128 + hb]);
        A2a1 = ffma2(rv1, w2.x, A2a1);  A2b1 = ffma2(rv1, w2.y, A2b1);
        A2a2 = ffma2(rv2, w2.x, A2a2);  A2b2 = ffma2(rv2, w2.y, A2b2);
        const ulonglong2 wf = *reinterpret_cast<const ulonglong2*>(&smf[O_WF + m * 128 + hb]);
        AFa1 = ffma2(rv1, wf.x, AFa1);  AFb1 = ffma2(rv1, wf.y, AFb1);
        AFa2 = ffma2(rv2, wf.x, AFa2);  AFb2 = ffma2(rv2, wf.y, AFb2);
      }
    }
    const float2 a1lo1 = unpack2(A1a1), a1hi1 = unpack2(A1b1);
    const float2 a1lo2 = unpack2(A1a2), a1hi2 = unpack2(A1b2);
    const float2 amlo1 = unpack2(AMa1), amhi1 = unpack2(AMb1);
    const float2 amlo2 = unpack2(AMa2), amhi2 = unpack2(AMb2);
    const float2 a2lo1 = unpack2(A2a1), a2hi1 = unpack2(A2b1);
    const float2 a2lo2 = unpack2(A2a2), a2hi2 = unpack2(A2b2);
    const float2 aflo1 = unpack2(AFa1), afhi1 = unpack2(AFb1);
    const float2 aflo2 = unpack2(AFa2), afhi2 = unpack2(AFb2);
    const float4 c1v = *reinterpret_cast<const float4*>(&smf[O_CF1 + hb]);
    const float4 c2v = *reinterpret_cast<const float4*>(&smf[O_CF2 + hb]);
    const float4 cfv = *reinterpret_cast<const float4*>(&smf[O_CFF + hb]);
    const float4 w21 = *reinterpret_cast<const float4*>(&smf[O_V21 + hb]);
    const float4 w22 = *reinterpret_cast<const float4*>(&smf[O_V22 + hb]);
    EPI(a1lo1.x, amlo1.x, a2lo1.x, aflo1.x, a1lo2.x, amlo2.x, a2lo2.x, aflo2.x,
        c1v.x, c2v.x, cfv.x, w21.x, w22.x, hb + 0);
    EPI(a1lo1.y, amlo1.y, a2lo1.y, aflo1.y, a1lo2.y, amlo2.y, a2lo2.y, aflo2.y,
        c1v.y, c2v.y, cfv.y, w21.y, w22.y, hb + 1);
    EPI(a1hi1.x, amhi1.x, a2hi1.x, afhi1.x, a1hi2.x, amhi2.x, a2hi2.x, afhi2.x,
        c1v.z, c2v.z, cfv.z, w21.z, w22.z, hb + 2);
    EPI(a1hi1.y, amhi1.y, a2hi1.y, afhi1.y, a1hi2.y, amhi2.y, a2hi2.y, afhi2.y,
        c1v.w, c2v.w, cfv.w, w21.w, w22.w, hb + 3);
  }

  // --- per-thread scalar outputs ---
  const float b2s1 = s1b2[0], b2s2 = s2b2[0];
  const float s1v1 = s1a1 + b2s1;
  const float s2v1 = s2a1 + b2s2;
  const float gd1 = -2.f * gam * da1 * __fdividef(rr1, d1);
  const float s1v2 = (s1a2 + b2s1) * act2;
  const float s2v2 = (s2a2 + b2s2) * act2;
  const float gd2 = -2.f * gam * da2 * __fdividef(rr2q, d2) * act2;

  float vals[7];
  vals[0] = fmaf(s1v2, rx2, s1v1 * rx1);
  vals[1] = fmaf(s1v2, ry2, s1v1 * ry1);
  vals[2] = fmaf(s1v2, rz2, s1v1 * rz1);
  vals[3] = fmaf(s2v2, rx2, s2v1 * rx1);
  vals[4] = fmaf(s2v2, ry2, s2v1 * ry1);
  vals[5] = fmaf(s2v2, rz2, s2v1 * rz1);
  vals[6] = gd1 + 3.f * s1v1 + gd2 + 3.f * s1v2;

  #pragma unroll
  for (int c = 0; c < 7; c++) {
    float v = vals[c];
    #pragma unroll
    for (int o = 16; o; o >>= 1) v += __shfl_xor_sync(0xffffffffu, v, o);
    vals[c] = v;
  }
  if (lane == 0) {
    #pragma unroll
    for (int c = 0; c < 7; c++) smf[O_RED + wid * 8 + c] = vals[c];
  }
  __syncthreads();
  if (tid < 7) {
    float s = 0.f;
    #pragma unroll
    for (int w = 0; w < 4; w++) s += smf[O_RED + w * 8 + tid];
    smf[O_TOT + tid] = s;
  }
  {
    float s = 0.f;
    #pragma unroll
    for (int w = 0; w < 4; w++) s += smf[O_HS + w * 128 + tid];
    smf[O_HT + tid] = s;
  }
  __syncthreads();

  if (tid == 0) {
    const float inv = 1.f / (float)NK;
    const float v1x = smf[O_TOT + 0] * inv;
    const float v1y = smf[O_TOT + 1] * inv;
    const float v1z = smf[O_TOT + 2] * inv;
    const float m2x = smf[O_TOT + 3] * inv;
    const float m2y = smf[O_TOT + 4] * inv;
    const float m2z = smf[O_TOT + 5] * inv;
    g_vx[bi * 3 + 0] = v1x + (m2y * v1z - m2z * v1y);
    g_vx[bi * 3 + 1] = v1y + (m2z * v1x - m2x * v1z);
    g_vx[bi * 3 + 2] = v1z + (m2x * v1y - m2y * v1x);
    g_tr[bi] = smf[O_TOT + 6];
  }
  if (tid < 32) {
    float acc = 0.f;
    #pragma unroll 8
    for (int h = 0; h < 128; h++) acc = fmaf(smf[O_HT + h], fW2[h * 32 + tid], acc);
    out[b * SD + 768 + i * 32 + tid] = acc * (1.f / (float)NK) + fb2[tid];
  }
}

__global__ __launch_bounds__(256) void fd_final(float* __restrict__ out)
{
  __shared__ float red[8][4];
  __shared__ float tot[4];
  const int b = blockIdx.x, tid = threadIdx.x;
  const float v0 = g_vx[(b * NPTS + tid) * 3 + 0];
  const float v1 = g_vx[(b * NPTS + tid) * 3 + 1];
  const float v2 = g_vx[(b * NPTS + tid) * 3 + 2];
  const float v3 = g_tr[b * NPTS + tid];
  float r0 = v0, r1 = v1, r2 = v2, r3 = v3;
  #pragma unroll
  for (int o = 16; o; o >>= 1) {
    r0 += __shfl_xor_sync(0xffffffffu, r0, o);
    r1 += __shfl_xor_sync(0xffffffffu, r1, o);
    r2 += __shfl_xor_sync(0xffffffffu, r2, o);
    r3 += __shfl_xor_sync(0xffffffffu, r3, o);
  }
  const int wid = tid >> 5, lane = tid & 31;
  if (lane == 0) { red[wid][0] = r0; red[wid][1] = r1; red[wid][2] = r2; red[wid][3] = r3; }
  __syncthreads();
  if (tid < 4) {
    float s = 0.f;
    #pragma unroll
    for (int w = 0; w < 8; w++) s += red[w][tid];
    tot[tid] = s;
  }
  __syncthreads();
  const float invn = 1.f / (float)NPTS;
  out[b * SD + tid * 3 + 0] = v0 - tot[0] * invn;
  out[b * SD + tid * 3 + 1] = v1 - tot[1] * invn;
  out[b * SD + tid * 3 + 2] = v2 - tot[2] * invn;
  if (tid == 0) out[NBATCH * SD + b] = tot[3] * (1.f / (float)NK);
}

extern "C" void kernel_launch(void* const* d_in, const int* in_sizes, int n_in,
                              void* d_out, int out_size)
{
  const float* state = (const float*)d_in[1];
  const float* mus   = (const float*)d_in[2];
  const float* gam   = (const float*)d_in[3];
  const float* s1W1  = (const float*)d_in[4];
  const float* s1b1  = (const float*)d_in[5];
  const float* s1W2  = (const float*)d_in[6];
  const float* s1b2  = (const float*)d_in[7];
  const float* s2W1  = (const float*)d_in[8];
  const float* s2b1  = (const float*)d_in[9];
  const float* s2W2  = (const float*)d_in[10];
  const float* s2b2  = (const float*)d_in[11];
  const float* fW1   = (const float*)d_in[12];
  const float* fb1   = (const float*)d_in[13];
  const float* fW2   = (const float*)d_in[14];
  const float* fb2   = (const float*)d_in[15];
  float* out = (float*)d_out;

  const int smem_bytes = SMEM_FLOATS * (int)sizeof(float);
  cudaFuncSetAttribute(fd_main, cudaFuncAttributeMaxDynamicSharedMemorySize, smem_bytes);
  fd_main<<<NBATCH * NPTS, 128, smem_bytes>>>(
      state, mus, gam,
      s1W1, s1b1, s1W2, s1b2,
      s2W1, s2b1, s2W2, s2b2,
      fW1, fb1, fW2, fb2, out);
  fd_final<<<NBATCH, 256>>>(out);
}

// round 14
// speedup vs baseline: 1.5477x; 1.5477x over previous
#include <cuda_runtime.h>
#include <math.h>

#define NBATCH 8
#define NPTS   256
#define NRBF_  50
#define NK     255
#define SD     8960

__device__ float g_vx[NBATCH * NPTS * 3];
__device__ float g_tr[NBATCH * NPTS];

typedef unsigned long long u64;

__device__ __forceinline__ u64 pack2(float x, float y) {
  u64 r; asm("mov.b64 %0,{%1,%2};" : "=l"(r) : "f"(x), "f"(y)); return r;
}
__device__ __forceinline__ float2 unpack2(u64 v) {
  float2 f; asm("mov.b64 {%0,%1},%2;" : "=f"(f.x), "=f"(f.y) : "l"(v)); return f;
}
__device__ __forceinline__ u64 ffma2(u64 a, u64 b, u64 c) {
  u64 d; asm("fma.rn.f32x2 %0,%1,%2,%3;" : "=l"(d) : "l"(a), "l"(b), "l"(c)); return d;
}
__device__ __forceinline__ float sgm(float z) {  // sigmoid via tanh (1 MUFU)
  float t; asm("tanh.approx.f32 %0, %1;" : "=f"(t) : "f"(0.5f * z));
  return fmaf(0.5f, t, 0.5f);
}

// ---- shared memory layout (floats) ----
#define O_W1   0
#define O_WM   (O_W1 + 6400)
#define O_W2   (O_WM + 6400)
#define O_WF   (O_W2 + 6400)
#define O_V21  (O_WF + 6400)
#define O_V22  (O_V21 + 128)
#define O_CF1  (O_V22 + 128)
#define O_CF2  (O_CF1 + 128)
#define O_CFF  (O_CF2 + 128)
#define O_XS   (O_CFF + 128)
#define O_FS   (O_XS + 768)
#define O_SMX  (O_FS + 32)
#define O_MUS  (O_SMX + 32)
#define O_HS   (O_MUS + 64)
#define O_HT   (O_HS + 512)
#define O_RED  (O_HT + 128)
#define O_TOT  (O_RED + 32)
#define SMEM_FLOATS (O_TOT + 8)

__global__ __launch_bounds__(128, 2) void fd_main(
    const float* __restrict__ state, const float* __restrict__ mus,
    const float* __restrict__ gamma_p,
    const float* __restrict__ s1W1, const float* __restrict__ s1b1,
    const float* __restrict__ s1W2, const float* __restrict__ s1b2,
    const float* __restrict__ s2W1, const float* __restrict__ s2b1,
    const float* __restrict__ s2W2, const float* __restrict__ s2b2,
    const float* __restrict__ fW1, const float* __restrict__ fb1,
    const float* __restrict__ fW2, const float* __restrict__ fb2,
    float* __restrict__ out)
{
  extern __shared__ float smf[];
  const int tid = threadIdx.x;
  const int wid = tid >> 5, lane = tid & 31;
  const int bi = blockIdx.x;
  const int b = bi >> 8;
  const int i = bi & 255;
  const float gam = gamma_p[0];

  // --- stage weights / inputs into smem ---
  for (int idx = tid; idx < 6400; idx += 128) {
    float w = s1W1[idx];
    smf[O_W1 + idx] = w;
    smf[O_WM + idx] = w * mus[idx >> 7];
    smf[O_W2 + idx] = s2W1[idx];
    smf[O_WF + idx] = fW1[idx];
  }
  smf[O_V21 + tid] = s1W2[tid];
  smf[O_V22 + tid] = s2W2[tid];
  for (int idx = tid; idx < 512; idx += 128) smf[O_HS + idx] = 0.f;
  for (int idx = tid; idx < 768; idx += 128) smf[O_XS + idx] = state[b * SD + idx];
  if (tid < 32) smf[O_FS + tid] = state[b * SD + 768 + i * 32 + tid];
  if (tid < 64) smf[O_MUS + tid] = (tid < NRBF_) ? mus[tid] : 0.f;
  __syncthreads();

  // softmax(feats) by warp 0
  if (tid < 32) {
    float v = smf[O_FS + tid];
    float mx = v;
    #pragma unroll
    for (int o = 16; o; o >>= 1) mx = fmaxf(mx, __shfl_xor_sync(0xffffffffu, mx, o));
    float e = __expf(v - mx);
    float s = e;
    #pragma unroll
    for (int o = 16; o; o >>= 1) s += __shfl_xor_sync(0xffffffffu, s, o);
    smf[O_SMX + tid] = __fdividef(e, s);
  }
  __syncthreads();

  // per-(b,i) constant hidden contributions (feat columns + bias), one lane per h
  {
    const int h = tid;
    float c1 = s1b1[h], c2 = s2b1[h], cf = fb1[h];
    #pragma unroll 4
    for (int f = 0; f < 32; f++) {
      float fv = smf[O_FS + f];
      c1 = fmaf(fv, s1W1[(50 + f) * 128 + h] + s1W1[(82 + f) * 128 + h], c1);
      c2 = fmaf(fv, s2W1[(50 + f) * 128 + h] + s2W1[(82 + f) * 128 + h], c2);
      cf = fmaf(smf[O_SMX + f], fW1[(50 + f) * 128 + h], cf);
    }
    smf[O_CF1 + h] = c1;
    smf[O_CF2 + h] = c2;
    smf[O_CFF + h] = cf;
  }
  __syncthreads();

  // --- each thread handles neighbors k1 = tid and k2 = tid+128 ---
  const int k1 = tid;
  const int k2t = tid + 128;
  const float act2 = (k2t < NK) ? 1.f : 0.f;
  const int k2 = (k2t < NK) ? k2t : NK - 1;
  const int j1 = (k1 < i) ? k1 : k1 + 1;
  const int j2 = (k2 < i) ? k2 : k2 + 1;
  const float xi0 = smf[O_XS + i * 3 + 0];
  const float xi1 = smf[O_XS + i * 3 + 1];
  const float xi2 = smf[O_XS + i * 3 + 2];
  const float rx1 = xi0 - smf[O_XS + j1 * 3 + 0];
  const float ry1 = xi1 - smf[O_XS + j1 * 3 + 1];
  const float rz1 = xi2 - smf[O_XS + j1 * 3 + 2];
  const float rx2 = xi0 - smf[O_XS + j2 * 3 + 0];
  const float ry2 = xi1 - smf[O_XS + j2 * 3 + 1];
  const float rz2 = xi2 - smf[O_XS + j2 * 3 + 2];
  const float rr1 = rx1 * rx1 + ry1 * ry1 + rz1 * rz1;
  const float rr2q = rx2 * rx2 + ry2 * ry2 + rz2 * rz2;
  const float d1 = sqrtf(rr1 + 1e-6f);
  const float d2 = sqrtf(rr2q + 1e-6f);

  float rbf1[NRBF_], rbf2[NRBF_];
  #pragma unroll
  for (int m = 0; m < NRBF_; m++) {
    float mu = smf[O_MUS + m];
    float dm1 = d1 - mu, dm2 = d2 - mu;
    rbf1[m] = __expf(-gam * dm1 * dm1);
    rbf2[m] = __expf(-gam * dm2 * dm2);
  }

  float s1a1 = 0.f, s1a2 = 0.f, s2a1 = 0.f, s2a2 = 0.f, da1 = 0.f, da2 = 0.f;

  // hb-block of 8 hidden lanes: acc[panel][neighbor][pair]  (pair = 2 h-lanes)
  #pragma unroll 1
  for (int hb = 0; hb < 128; hb += 8) {
    u64 acc[4][2][4];
    #pragma unroll
    for (int p = 0; p < 4; p++)
      #pragma unroll
      for (int n = 0; n < 2; n++)
        #pragma unroll
        for (int q = 0; q < 4; q++) acc[p][n][q] = 0ull;

    #pragma unroll
    for (int m = 0; m < NRBF_; m++) {
      const u64 rv1 = pack2(rbf1[m], rbf1[m]);
      const u64 rv2 = pack2(rbf2[m], rbf2[m]);
      {
        const ulonglong2 lo = *reinterpret_cast<const ulonglong2*>(&smf[O_W1 + m * 128 + hb]);
        const ulonglong2 hi = *reinterpret_cast<const ulonglong2*>(&smf[O_W1 + m * 128 + hb + 4]);
        acc[0][0][0] = ffma2(rv1, lo.x, acc[0][0][0]); acc[0][0][1] = ffma2(rv1, lo.y, acc[0][0][1]);
        acc[0][0][2] = ffma2(rv1, hi.x, acc[0][0][2]); acc[0][0][3] = ffma2(rv1, hi.y, acc[0][0][3]);
        acc[0][1][0] = ffma2(rv2, lo.x, acc[0][1][0]); acc[0][1][1] = ffma2(rv2, lo.y, acc[0][1][1]);
        acc[0][1][2] = ffma2(rv2, hi.x, acc[0][1][2]); acc[0][1][3] = ffma2(rv2, hi.y, acc[0][1][3]);
      }
      {
        const ulonglong2 lo = *reinterpret_cast<const ulonglong2*>(&smf[O_WM + m * 128 + hb]);
        const ulonglong2 hi = *reinterpret_cast<const ulonglong2*>(&smf[O_WM + m * 128 + hb + 4]);
        acc[1][0][0] = ffma2(rv1, lo.x, acc[1][0][0]); acc[1][0][1] = ffma2(rv1, lo.y, acc[1][0][1]);
        acc[1][0][2] = ffma2(rv1, hi.x, acc[1][0][2]); acc[1][0][3] = ffma2(rv1, hi.y, acc[1][0][3]);
        acc[1][1][0] = ffma2(rv2, lo.x, acc[1][1][0]); acc[1][1][1] = ffma2(rv2, lo.y, acc[1][1][1]);
        acc[1][1][2] = ffma2(rv2, hi.x, acc[1][1][2]); acc[1][1][3] = ffma2(rv2, hi.y, acc[1][1][3]);
      }
      {
        const ulonglong2 lo = *reinterpret_cast<const ulonglong2*>(&smf[O_W2 + m * 128 + hb]);
        const ulonglong2 hi = *reinterpret_cast<const ulonglong2*>(&smf[O_W2 + m * 128 + hb + 4]);
        acc[2][0][0] = ffma2(rv1, lo.x, acc[2][0][0]); acc[2][0][1] = ffma2(rv1, lo.y, acc[2][0][1]);
        acc[2][0][2] = ffma2(rv1, hi.x, acc[2][0][2]); acc[2][0][3] = ffma2(rv1, hi.y, acc[2][0][3]);
        acc[2][1][0] = ffma2(rv2, lo.x, acc[2][1][0]); acc[2][1][1] = ffma2(rv2, lo.y, acc[2][1][1]);
        acc[2][1][2] = ffma2(rv2, hi.x, acc[2][1][2]); acc[2][1][3] = ffma2(rv2, hi.y, acc[2][1][3]);
      }
      {
        const ulonglong2 lo = *reinterpret_cast<const ulonglong2*>(&smf[O_WF + m * 128 + hb]);
        const ulonglong2 hi = *reinterpret_cast<const ulonglong2*>(&smf[O_WF + m * 128 + hb + 4]);
        acc[3][0][0] = ffma2(rv1, lo.x, acc[3][0][0]); acc[3][0][1] = ffma2(rv1, lo.y, acc[3][0][1]);
        acc[3][0][2] = ffma2(rv1, hi.x, acc[3][0][2]); acc[3][0][3] = ffma2(rv1, hi.y, acc[3][0][3]);
        acc[3][1][0] = ffma2(rv2, lo.x, acc[3][1][0]); acc[3][1][1] = ffma2(rv2, lo.y, acc[3][1][1]);
        acc[3][1][2] = ffma2(rv2, hi.x, acc[3][1][2]); acc[3][1][3] = ffma2(rv2, hi.y, acc[3][1][3]);
      }
    }

    // unpack accumulators into per-h arrays (e = 0..7)
    float A1n1[8], A1n2[8], AMn1[8], AMn2[8], A2n1[8], A2n2[8], AFn1[8], AFn2[8];
    #pragma unroll
    for (int q = 0; q < 4; q++) {
      float2 v;
      v = unpack2(acc[0][0][q]); A1n1[2 * q] = v.x; A1n1[2 * q + 1] = v.y;
      v = unpack2(acc[0][1][q]); A1n2[2 * q] = v.x; A1n2[2 * q + 1] = v.y;
      v = unpack2(acc[1][0][q]); AMn1[2 * q] = v.x; AMn1[2 * q + 1] = v.y;
      v = unpack2(acc[1][1][q]); AMn2[2 * q] = v.x; AMn2[2 * q + 1] = v.y;
      v = unpack2(acc[2][0][q]); A2n1[2 * q] = v.x; A2n1[2 * q + 1] = v.y;
      v = unpack2(acc[2][1][q]); A2n2[2 * q] = v.x; A2n2[2 * q + 1] = v.y;
      v = unpack2(acc[3][0][q]); AFn1[2 * q] = v.x; AFn1[2 * q + 1] = v.y;
      v = unpack2(acc[3][1][q]); AFn2[2 * q] = v.x; AFn2[2 * q + 1] = v.y;
    }
    float c1a[8], c2a[8], cfa[8], w21a[8], w22a[8];
    #pragma unroll
    for (int half = 0; half < 2; half++) {
      const float4 c1v = *reinterpret_cast<const float4*>(&smf[O_CF1 + hb + 4 * half]);
      const float4 c2v = *reinterpret_cast<const float4*>(&smf[O_CF2 + hb + 4 * half]);
      const float4 cfv = *reinterpret_cast<const float4*>(&smf[O_CFF + hb + 4 * half]);
      const float4 w1v = *reinterpret_cast<const float4*>(&smf[O_V21 + hb + 4 * half]);
      const float4 w2v = *reinterpret_cast<const float4*>(&smf[O_V22 + hb + 4 * half]);
      c1a[4 * half + 0] = c1v.x; c1a[4 * half + 1] = c1v.y; c1a[4 * half + 2] = c1v.z; c1a[4 * half + 3] = c1v.w;
      c2a[4 * half + 0] = c2v.x; c2a[4 * half + 1] = c2v.y; c2a[4 * half + 2] = c2v.z; c2a[4 * half + 3] = c2v.w;
      cfa[4 * half + 0] = cfv.x; cfa[4 * half + 1] = cfv.y; cfa[4 * half + 2] = cfv.z; cfa[4 * half + 3] = cfv.w;
      w21a[4 * half + 0] = w1v.x; w21a[4 * half + 1] = w1v.y; w21a[4 * half + 2] = w1v.z; w21a[4 * half + 3] = w1v.w;
      w22a[4 * half + 0] = w2v.x; w22a[4 * half + 1] = w2v.y; w22a[4 * half + 2] = w2v.z; w22a[4 * half + 3] = w2v.w;
    }

    // epilogue: 8 independent h-lanes
    float slf8[8];
    #pragma unroll
    for (int e = 0; e < 8; e++) {
      const float z1a = A1n1[e] + c1a[e];
      const float sga = sgm(z1a);
      s1a1 = fmaf(z1a * sga, w21a[e], s1a1);
      const float spa = sga * fmaf(z1a, 1.f - sga, 1.f);
      da1 = fmaf(w21a[e] * spa, fmaf(d1, A1n1[e], -AMn1[e]), da1);
      const float z1b = A1n2[e] + c1a[e];
      const float sgb = sgm(z1b);
      s1a2 = fmaf(z1b * sgb, w21a[e], s1a2);
      const float spb = sgb * fmaf(z1b, 1.f - sgb, 1.f);
      da2 = fmaf(w21a[e] * spb, fmaf(d2, A1n2[e], -AMn2[e]), da2);
      const float z2a = A2n1[e] + c2a[e];
      s2a1 = fmaf(z2a * sgm(z2a), w22a[e], s2a1);
      const float z2b = A2n2[e] + c2a[e];
      s2a2 = fmaf(z2b * sgm(z2b), w22a[e], s2a2);
      const float zfa = AFn1[e] + cfa[e];
      const float zfb = AFn2[e] + cfa[e];
      slf8[e] = fmaf(zfb * sgm(zfb), act2, zfa * sgm(zfa));
    }
    // 8 independent shfl-reduce chains
    #pragma unroll
    for (int e = 0; e < 8; e++) {
      float v = slf8[e];
      #pragma unroll
      for (int o = 16; o; o >>= 1) v += __shfl_xor_sync(0xffffffffu, v, o);
      slf8[e] = v;
    }
    if (lane == 0) {
      #pragma unroll
      for (int e = 0; e < 8; e++) smf[O_HS + wid * 128 + hb + e] += slf8[e];
    }
  }

  // --- per-thread scalar outputs, both neighbors folded together ---
  const float b2s1 = s1b2[0], b2s2 = s2b2[0];
  const float s1v1 = s1a1 + b2s1;
  const float s2v1 = s2a1 + b2s2;
  const float gd1 = -2.f * gam * da1 * __fdividef(rr1, d1);
  const float s1v2 = (s1a2 + b2s1) * act2;
  const float s2v2 = (s2a2 + b2s2) * act2;
  const float gd2 = -2.f * gam * da2 * __fdividef(rr2q, d2) * act2;

  float vals[7];
  vals[0] = fmaf(s1v2, rx2, s1v1 * rx1);
  vals[1] = fmaf(s1v2, ry2, s1v1 * ry1);
  vals[2] = fmaf(s1v2, rz2, s1v1 * rz1);
  vals[3] = fmaf(s2v2, rx2, s2v1 * rx1);
  vals[4] = fmaf(s2v2, ry2, s2v1 * ry1);
  vals[5] = fmaf(s2v2, rz2, s2v1 * rz1);
  vals[6] = gd1 + 3.f * s1v1 + gd2 + 3.f * s1v2;

  #pragma unroll
  for (int c = 0; c < 7; c++) {
    float v = vals[c];
    #pragma unroll
    for (int o = 16; o; o >>= 1) v += __shfl_xor_sync(0xffffffffu, v, o);
    vals[c] = v;
  }
  if (lane == 0) {
    #pragma unroll
    for (int c = 0; c < 7; c++) smf[O_RED + wid * 8 + c] = vals[c];
  }
  __syncthreads();
  if (tid < 7) {
    float s = 0.f;
    #pragma unroll
    for (int w = 0; w < 4; w++) s += smf[O_RED + w * 8 + tid];
    smf[O_TOT + tid] = s;
  }
  {
    float s = 0.f;
    #pragma unroll
    for (int w = 0; w < 4; w++) s += smf[O_HS + w * 128 + tid];
    smf[O_HT + tid] = s;
  }
  __syncthreads();

  if (tid == 0) {
    const float inv = 1.f / (float)NK;
    const float v1x = smf[O_TOT + 0] * inv;
    const float v1y = smf[O_TOT + 1] * inv;
    const float v1z = smf[O_TOT + 2] * inv;
    const float m2x = smf[O_TOT + 3] * inv;
    const float m2y = smf[O_TOT + 4] * inv;
    const float m2z = smf[O_TOT + 5] * inv;
    g_vx[bi * 3 + 0] = v1x + (m2y * v1z - m2z * v1y);
    g_vx[bi * 3 + 1] = v1y + (m2z * v1x - m2x * v1z);
    g_vx[bi * 3 + 2] = v1z + (m2x * v1y - m2y * v1x);
    g_tr[bi] = smf[O_TOT + 6];
  }
  if (tid < 32) {
    float acc = 0.f;
    #pragma unroll 8
    for (int h = 0; h < 128; h++) acc = fmaf(smf[O_HT + h], fW2[h * 32 + tid], acc);
    out[b * SD + 768 + i * 32 + tid] = acc * (1.f / (float)NK) + fb2[tid];
  }
}

__global__ __launch_bounds__(256) void fd_final(float* __restrict__ out)
{
  __shared__ float red[8][4];
  __shared__ float tot[4];
  const int b = blockIdx.x, tid = threadIdx.x;
  const float v0 = g_vx[(b * NPTS + tid) * 3 + 0];
  const float v1 = g_vx[(b * NPTS + tid) * 3 + 1];
  const float v2 = g_vx[(b * NPTS + tid) * 3 + 2];
  const float v3 = g_tr[b * NPTS + tid];
  float r0 = v0, r1 = v1, r2 = v2, r3 = v3;
  #pragma unroll
  for (int o = 16; o; o >>= 1) {
    r0 += __shfl_xor_sync(0xffffffffu, r0, o);
    r1 += __shfl_xor_sync(0xffffffffu, r1, o);
    r2 += __shfl_xor_sync(0xffffffffu, r2, o);
    r3 += __shfl_xor_sync(0xffffffffu, r3, o);
  }
  const int wid = tid >> 5, lane = tid & 31;
  if (lane == 0) { red[wid][0] = r0; red[wid][1] = r1; red[wid][2] = r2; red[wid][3] = r3; }
  __syncthreads();
  if (tid < 4) {
    float s = 0.f;
    #pragma unroll
    for (int w = 0; w < 8; w++) s += red[w][tid];
    tot[tid] = s;
  }
  __syncthreads();
  const float invn = 1.f / (float)NPTS;
  out[b * SD + tid * 3 + 0] = v0 - tot[0] * invn;
  out[b * SD + tid * 3 + 1] = v1 - tot[1] * invn;
  out[b * SD + tid * 3 + 2] = v2 - tot[2] * invn;
  if (tid == 0) out[NBATCH * SD + b] = tot[3] * (1.f / (float)NK);
}

extern "C" void kernel_launch(void* const* d_in, const int* in_sizes, int n_in,
                              void* d_out, int out_size)
{
  const float* state = (const float*)d_in[1];
  const float* mus   = (const float*)d_in[2];
  const float* gam   = (const float*)d_in[3];
  const float* s1W1  = (const float*)d_in[4];
  const float* s1b1  = (const float*)d_in[5];
  const float* s1W2  = (const float*)d_in[6];
  const float* s1b2  = (const float*)d_in[7];
  const float* s2W1  = (const float*)d_in[8];
  const float* s2b1  = (const float*)d_in[9];
  const float* s2W2  = (const float*)d_in[10];
  const float* s2b2  = (const float*)d_in[11];
  const float* fW1   = (const float*)d_in[12];
  const float* fb1   = (const float*)d_in[13];
  const float* fW2   = (const float*)d_in[14];
  const float* fb2   = (const float*)d_in[15];
  float* out = (float*)d_out;

  const int smem_bytes = SMEM_FLOATS * (int)sizeof(float);
  cudaFuncSetAttribute(fd_main, cudaFuncAttributeMaxDynamicSharedMemorySize, smem_bytes);
  fd_main<<<NBATCH * NPTS, 128, smem_bytes>>>(
      state, mus, gam,
      s1W1, s1b1, s1W2, s1b2,
      s2W1, s2b1, s2W2, s2b2,
      fW1, fb1, fW2, fb2, out);
  fd_final<<<NBATCH, 256>>>(out);
}

// round 15
// speedup vs baseline: 1.9275x; 1.2454x over previous
#include <cuda_runtime.h>
#include <math.h>

#define NBATCH 8
#define NPTS 256
#define NRBF_ 50
#define NK 255
#define SD 8960
#define NSITES 2048

// ---- device scratch (static, allowed) ----
__device__ float g_c[NSITES * 128 * 4];     // per-site {c1,c2,cf,0} per h
__device__ float g_sj[NSITES * 128 * 8];    // j-side 7 scalars per (site,slot)
__device__ float g_fj[NSITES * 128 * 128];  // j-side silu(zf) per (site,slot,h)
__device__ float g_si[NSITES * 8];          // i-side reduced 7 per site
__device__ float g_hi[NSITES * 128];        // i-side f hidden sums per site
__device__ float g_vx[NSITES * 3];
__device__ float g_tr[NSITES];

typedef unsigned long long u64;

__device__ __forceinline__ u64 pack2(float x, float y) {
  u64 r; asm("mov.b64 %0,{%1,%2};" : "=l"(r) : "f"(x), "f"(y)); return r;
}
__device__ __forceinline__ float2 unpack2(u64 v) {
  float2 f; asm("mov.b64 {%0,%1},%2;" : "=f"(f.x), "=f"(f.y) : "l"(v)); return f;
}
__device__ __forceinline__ u64 ffma2(u64 a, u64 b, u64 c) {
  u64 d; asm("fma.rn.f32x2 %0,%1,%2,%3;" : "=l"(d) : "l"(a), "l"(b), "l"(c)); return d;
}
__device__ __forceinline__ float sgm(float z) {
  float t; asm("tanh.approx.f32 %0, %1;" : "=f"(t) : "f"(0.5f * z));
  return fmaf(0.5f, t, 0.5f);
}

// ================= kernel A: per-site constants =================
__global__ __launch_bounds__(128) void fd_prep(
    const float* __restrict__ state,
    const float* __restrict__ s1W1, const float* __restrict__ s1b1,
    const float* __restrict__ s2W1, const float* __restrict__ s2b1,
    const float* __restrict__ fW1, const float* __restrict__ fb1)
{
  const int gs = blockIdx.x, b = gs >> 8, site = gs & 255;
  const int h = threadIdx.x;
  __shared__ float fs[32], smx[32];
  if (h < 32) fs[h] = state[b * SD + 768 + site * 32 + h];
  __syncthreads();
  if (h < 32) {
    float v = fs[h], mx = v;
    #pragma unroll
    for (int o = 16; o; o >>= 1) mx = fmaxf(mx, __shfl_xor_sync(0xffffffffu, mx, o));
    float e = __expf(v - mx), s = e;
    #pragma unroll
    for (int o = 16; o; o >>= 1) s += __shfl_xor_sync(0xffffffffu, s, o);
    smx[h] = __fdividef(e, s);
  }
  __syncthreads();
  float c1 = s1b1[h], c2 = s2b1[h], cf = fb1[h];
  #pragma unroll 4
  for (int f = 0; f < 32; f++) {
    float fv = fs[f];
    c1 = fmaf(fv, s1W1[(50 + f) * 128 + h] + s1W1[(82 + f) * 128 + h], c1);
    c2 = fmaf(fv, s2W1[(50 + f) * 128 + h] + s2W1[(82 + f) * 128 + h], c2);
    cf = fmaf(smx[f], fW1[(50 + f) * 128 + h], cf);
  }
  ((float4*)g_c)[gs * 128 + h] = make_float4(c1, c2, cf, 0.f);
  if (site < 128) {  // slot 0 has no active writer for these sites
    g_fj[(gs * 128 + 0) * 128 + h] = 0.f;
    if (h < 8) g_sj[(gs * 128 + 0) * 8 + h] = 0.f;
  }
}

// ================= kernel B: pair blocks =================
#define O_W1 0
#define O_WM 6400
#define O_W2 12800
#define O_WF 19200
#define O_CS 25600   // float4[256]: [h]=site s0, [128+h]=site s1
#define O_V  26624   // float2[128] {s1W2, s2W2}
#define O_MUS 26880  // 64
#define O_HS 26944   // [4 warps][2 sites][128]
#define O_RED 27968  // 4*16
#define O_TOT 28032  // 16
#define SMEM_B 28048 // floats = 112192 B

__global__ __launch_bounds__(128, 2) void fd_pairs(
    const float* __restrict__ state, const float* __restrict__ mus,
    const float* __restrict__ gamma_p,
    const float* __restrict__ s1W1, const float* __restrict__ s1W2,
    const float* __restrict__ s1b2,
    const float* __restrict__ s2W1, const float* __restrict__ s2W2,
    const float* __restrict__ s2b2,
    const float* __restrict__ fW1)
{
  extern __shared__ float smf[];
  const int tid = threadIdx.x;
  const int wid = tid >> 5, lane = tid & 31;
  const int q = blockIdx.x & 127, b = blockIdx.x >> 7;
  const int s0 = 2 * q, s1 = 2 * q + 1;
  const float gam = gamma_p[0];

  for (int idx = tid; idx < 6400; idx += 128) {
    float w = s1W1[idx];
    smf[O_W1 + idx] = w;
    smf[O_WM + idx] = w * mus[idx >> 7];
    smf[O_W2 + idx] = s2W1[idx];
    smf[O_WF + idx] = fW1[idx];
  }
  for (int idx = tid; idx < 256; idx += 128) {
    int site = (idx < 128) ? s0 : s1;
    ((float4*)&smf[O_CS])[idx] = ((const float4*)g_c)[(b * 256 + site) * 128 + (idx & 127)];
  }
  ((float2*)&smf[O_V])[tid] = make_float2(s1W2[tid], s2W2[tid]);
  if (tid < 64) smf[O_MUS + tid] = (tid < NRBF_) ? mus[tid] : 0.f;
  for (int idx = tid; idx < 1024; idx += 128) smf[O_HS + idx] = 0.f;
  __syncthreads();

  // pair assignment: offset delta = tid+1 (1..128)
  const int dlt = tid + 1;
  const int j0 = (s0 + dlt) & 255;
  const int j1 = (s1 + dlt) & 255;
  const float act0 = (dlt < 128 || s0 < 128) ? 1.f : 0.f;
  const float act1 = (dlt < 128 || s1 < 128) ? 1.f : 0.f;
  const int slot = 127 - tid;
  const int bj0 = b * 256 + j0, bj1 = b * 256 + j1;
  const int gs0 = b * 256 + s0, gs1 = b * 256 + s1;

  const float* xs = state + b * SD;
  const float r0x = xs[s0 * 3 + 0] - xs[j0 * 3 + 0];
  const float r0y = xs[s0 * 3 + 1] - xs[j0 * 3 + 1];
  const float r0z = xs[s0 * 3 + 2] - xs[j0 * 3 + 2];
  const float r1x = xs[s1 * 3 + 0] - xs[j1 * 3 + 0];
  const float r1y = xs[s1 * 3 + 1] - xs[j1 * 3 + 1];
  const float r1z = xs[s1 * 3 + 2] - xs[j1 * 3 + 2];
  const float rr0 = r0x * r0x + r0y * r0y + r0z * r0z;
  const float rr1 = r1x * r1x + r1y * r1y + r1z * r1z;
  const float d0 = sqrtf(rr0 + 1e-6f);
  const float d1 = sqrtf(rr1 + 1e-6f);

  float rb0[NRBF_], rb1[NRBF_];
  #pragma unroll
  for (int m = 0; m < NRBF_; m++) {
    float mu = smf[O_MUS + m];
    float t0 = d0 - mu, t1 = d1 - mu;
    rb0[m] = __expf(-gam * t0 * t0);
    rb1[m] = __expf(-gam * t1 * t1);
  }

  float s1i0 = 0.f, s2i0 = 0.f, dai0 = 0.f, s1i1 = 0.f, s2i1 = 0.f, dai1 = 0.f;
  float s1j0 = 0.f, s2j0 = 0.f, daj0 = 0.f, s1j1 = 0.f, s2j1 = 0.f, daj1 = 0.f;

  #pragma unroll 1
  for (int hb = 0; hb < 128; hb += 4) {
    u64 A1a0 = 0, A1b0 = 0, A1a1 = 0, A1b1 = 0;
    u64 AMa0 = 0, AMb0 = 0, AMa1 = 0, AMb1 = 0;
    u64 A2a0 = 0, A2b0 = 0, A2a1 = 0, A2b1 = 0;
    u64 AFa0 = 0, AFb0 = 0, AFa1 = 0, AFb1 = 0;
    #pragma unroll
    for (int m = 0; m < NRBF_; m++) {
      const u64 rv0 = pack2(rb0[m], rb0[m]);
      const u64 rv1 = pack2(rb1[m], rb1[m]);
      const ulonglong2 w1 = *reinterpret_cast<const ulonglong2*>(&smf[O_W1 + m * 128 + hb]);
      A1a0 = ffma2(rv0, w1.x, A1a0);  A1b0 = ffma2(rv0, w1.y, A1b0);
      A1a1 = ffma2(rv1, w1.x, A1a1);  A1b1 = ffma2(rv1, w1.y, A1b1);
      const ulonglong2 wm = *reinterpret_cast<const ulonglong2*>(&smf[O_WM + m * 128 + hb]);
      AMa0 = ffma2(rv0, wm.x, AMa0);  AMb0 = ffma2(rv0, wm.y, AMb0);
      AMa1 = ffma2(rv1, wm.x, AMa1);  AMb1 = ffma2(rv1, wm.y, AMb1);
      const ulonglong2 w2 = *reinterpret_cast<const ulonglong2*>(&smf[O_W2 + m * 128 + hb]);
      A2a0 = ffma2(rv0, w2.x, A2a0);  A2b0 = ffma2(rv0, w2.y, A2b0);
      A2a1 = ffma2(rv1, w2.x, A2a1);  A2b1 = ffma2(rv1, w2.y, A2b1);
      const ulonglong2 wf = *reinterpret_cast<const ulonglong2*>(&smf[O_WF + m * 128 + hb]);
      AFa0 = ffma2(rv0, wf.x, AFa0);  AFb0 = ffma2(rv0, wf.y, AFb0);
      AFa1 = ffma2(rv1, wf.x, AFa1);  AFb1 = ffma2(rv1, wf.y, AFb1);
    }
    float A1[2][4], AM[2][4], A2[2][4], AF[2][4];
    { float2 v;
      v = unpack2(A1a0); A1[0][0] = v.x; A1[0][1] = v.y;
      v = unpack2(A1b0); A1[0][2] = v.x; A1[0][3] = v.y;
      v = unpack2(A1a1); A1[1][0] = v.x; A1[1][1] = v.y;
      v = unpack2(A1b1); A1[1][2] = v.x; A1[1][3] = v.y;
      v = unpack2(AMa0); AM[0][0] = v.x; AM[0][1] = v.y;
      v = unpack2(AMb0); AM[0][2] = v.x; AM[0][3] = v.y;
      v = unpack2(AMa1); AM[1][0] = v.x; AM[1][1] = v.y;
      v = unpack2(AMb1); AM[1][2] = v.x; AM[1][3] = v.y;
      v = unpack2(A2a0); A2[0][0] = v.x; A2[0][1] = v.y;
      v = unpack2(A2b0); A2[0][2] = v.x; A2[0][3] = v.y;
      v = unpack2(A2a1); A2[1][0] = v.x; A2[1][1] = v.y;
      v = unpack2(A2b1); A2[1][2] = v.x; A2[1][3] = v.y;
      v = unpack2(AFa0); AF[0][0] = v.x; AF[0][1] = v.y;
      v = unpack2(AFb0); AF[0][2] = v.x; AF[0][3] = v.y;
      v = unpack2(AFa1); AF[1][0] = v.x; AF[1][1] = v.y;
      v = unpack2(AFb1); AF[1][2] = v.x; AF[1][3] = v.y;
    }
    float fj0[4], fj1[4], si0[4], si1[4];
    #pragma unroll
    for (int e = 0; e < 4; e++) {
      const int h = hb + e;
      const float4 cs0 = ((const float4*)&smf[O_CS])[h];
      const float4 cs1 = ((const float4*)&smf[O_CS])[128 + h];
      const float2 wv = ((const float2*)&smf[O_V])[h];
      const float4 cj0 = __ldg(&((const float4*)g_c)[bj0 * 128 + h]);
      const float4 cj1 = __ldg(&((const float4*)g_c)[bj1 * 128 + h]);
      // pair0 i-side (site s0)
      { float z = A1[0][e] + cs0.x; float sg = sgm(z);
        s1i0 = fmaf(z * sg, wv.x, s1i0);
        float sp = sg * fmaf(z, 1.f - sg, 1.f);
        dai0 = fmaf(wv.x * sp, fmaf(d0, A1[0][e], -AM[0][e]), dai0);
        float z2 = A2[0][e] + cs0.y;
        s2i0 = fmaf(z2 * sgm(z2), wv.y, s2i0);
        float zf = AF[0][e] + cs0.z; si0[e] = zf * sgm(zf); }
      // pair0 j-side (site j0)
      { float z = A1[0][e] + cj0.x; float sg = sgm(z);
        s1j0 = fmaf(z * sg, wv.x, s1j0);
        float sp = sg * fmaf(z, 1.f - sg, 1.f);
        daj0 = fmaf(wv.x * sp, fmaf(d0, A1[0][e], -AM[0][e]), daj0);
        float z2 = A2[0][e] + cj0.y;
        s2j0 = fmaf(z2 * sgm(z2), wv.y, s2j0);
        float zf = AF[0][e] + cj0.z; fj0[e] = zf * sgm(zf) * act0; }
      // pair1 i-side (site s1)
      { float z = A1[1][e] + cs1.x; float sg = sgm(z);
        s1i1 = fmaf(z * sg, wv.x, s1i1);
        float sp = sg * fmaf(z, 1.f - sg, 1.f);
        dai1 = fmaf(wv.x * sp, fmaf(d1, A1[1][e], -AM[1][e]), dai1);
        float z2 = A2[1][e] + cs1.y;
        s2i1 = fmaf(z2 * sgm(z2), wv.y, s2i1);
        float zf = AF[1][e] + cs1.z; si1[e] = zf * sgm(zf); }
      // pair1 j-side (site j1)
      { float z = A1[1][e] + cj1.x; float sg = sgm(z);
        s1j1 = fmaf(z * sg, wv.x, s1j1);
        float sp = sg * fmaf(z, 1.f - sg, 1.f);
        daj1 = fmaf(wv.x * sp, fmaf(d1, A1[1][e], -AM[1][e]), daj1);
        float z2 = A2[1][e] + cj1.y;
        s2j1 = fmaf(z2 * sgm(z2), wv.y, s2j1);
        float zf = AF[1][e] + cj1.z; fj1[e] = zf * sgm(zf) * act1; }
    }
    // stage j-side f contributions (unique rows, aligned)
    *(float4*)&g_fj[(bj0 * 128 + slot) * 128 + hb] = make_float4(fj0[0], fj0[1], fj0[2], fj0[3]);
    *(float4*)&g_fj[(bj1 * 128 + slot) * 128 + hb] = make_float4(fj1[0], fj1[1], fj1[2], fj1[3]);
    // i-side f hidden sums (per-warp rows, deterministic)
    #pragma unroll
    for (int e = 0; e < 4; e++) {
      float v0 = si0[e] * act0, v1 = si1[e] * act1;
      #pragma unroll
      for (int o = 16; o; o >>= 1) {
        v0 += __shfl_xor_sync(0xffffffffu, v0, o);
        v1 += __shfl_xor_sync(0xffffffffu, v1, o);
      }
      if (lane == 0) {
        smf[O_HS + (wid * 2 + 0) * 128 + hb + e] += v0;
        smf[O_HS + (wid * 2 + 1) * 128 + hb + e] += v1;
      }
    }
  }

  const float b21 = s1b2[0], b22 = s2b2[0];
  // i-side reduced scalars (14 values: 7 per site)
  const float s1v0 = (s1i0 + b21) * act0, s2v0 = (s2i0 + b22) * act0;
  const float gd0 = -2.f * gam * dai0 * __fdividef(rr0, d0) * act0;
  const float s1v1 = (s1i1 + b21) * act1, s2v1 = (s2i1 + b22) * act1;
  const float gd1 = -2.f * gam * dai1 * __fdividef(rr1, d1) * act1;
  float vals[14];
  vals[0] = s1v0 * r0x; vals[1] = s1v0 * r0y; vals[2] = s1v0 * r0z;
  vals[3] = s2v0 * r0x; vals[4] = s2v0 * r0y; vals[5] = s2v0 * r0z;
  vals[6] = gd0 + 3.f * s1v0;
  vals[7] = s1v1 * r1x; vals[8] = s1v1 * r1y; vals[9] = s1v1 * r1z;
  vals[10] = s2v1 * r1x; vals[11] = s2v1 * r1y; vals[12] = s2v1 * r1z;
  vals[13] = gd1 + 3.f * s1v1;
  #pragma unroll
  for (int c = 0; c < 14; c++) {
    float v = vals[c];
    #pragma unroll
    for (int o = 16; o; o >>= 1) v += __shfl_xor_sync(0xffffffffu, v, o);
    vals[c] = v;
  }
  if (lane == 0) {
    #pragma unroll
    for (int c = 0; c < 14; c++) smf[O_RED + wid * 16 + c] = vals[c];
  }
  // j-side scalar staging (r_ji = -r_ij)
  {
    const float s1w = (s1j0 + b21) * act0, s2w = (s2j0 + b22) * act0;
    const float gdw = -2.f * gam * daj0 * __fdividef(rr0, d0) * act0;
    float4* o = (float4*)&g_sj[(bj0 * 128 + slot) * 8];
    o[0] = make_float4(-s1w * r0x, -s1w * r0y, -s1w * r0z, -s2w * r0x);
    o[1] = make_float4(-s2w * r0y, -s2w * r0z, gdw + 3.f * s1w, 0.f);
  }
  {
    const float s1w = (s1j1 + b21) * act1, s2w = (s2j1 + b22) * act1;
    const float gdw = -2.f * gam * daj1 * __fdividef(rr1, d1) * act1;
    float4* o = (float4*)&g_sj[(bj1 * 128 + slot) * 8];
    o[0] = make_float4(-s1w * r1x, -s1w * r1y, -s1w * r1z, -s2w * r1x);
    o[1] = make_float4(-s2w * r1y, -s2w * r1z, gdw + 3.f * s1w, 0.f);
  }
  __syncthreads();
  if (tid < 14) {
    float s = 0.f;
    #pragma unroll
    for (int w = 0; w < 4; w++) s += smf[O_RED + w * 16 + tid];
    if (tid < 7) g_si[gs0 * 8 + tid] = s;
    else g_si[gs1 * 8 + tid - 7] = s;
  }
  {
    float h0 = 0.f, h1 = 0.f;
    #pragma unroll
    for (int w = 0; w < 4; w++) {
      h0 += smf[O_HS + (w * 2 + 0) * 128 + tid];
      h1 += smf[O_HS + (w * 2 + 1) * 128 + tid];
    }
    g_hi[gs0 * 128 + tid] = h0;
    g_hi[gs1 * 128 + tid] = h1;
  }
}

// ================= kernel C: per-site combine =================
__global__ __launch_bounds__(256) void fd_comb(
    const float* __restrict__ fW2, const float* __restrict__ fb2,
    float* __restrict__ out)
{
  const int gs = blockIdx.x, b = gs >> 8, site = gs & 255;
  const int tid = threadIdx.x, wid = tid >> 5, lane = tid & 31;
  __shared__ float P[256 * 16];
  __shared__ float HT[128];
  __shared__ float red[8 * 8];
  __shared__ float tot[8];

  // 7 j-side scalars summed over slots
  float v[7] = {0.f, 0.f, 0.f, 0.f, 0.f, 0.f, 0.f};
  if (tid < 128) {
    const float4* p = (const float4*)&g_sj[(gs * 128 + tid) * 8];
    float4 a = p[0], bb = p[1];
    v[0] = a.x; v[1] = a.y; v[2] = a.z; v[3] = a.w;
    v[4] = bb.x; v[5] = bb.y; v[6] = bb.z;
  }
  #pragma unroll
  for (int c = 0; c < 7; c++) {
    float x = v[c];
    #pragma unroll
    for (int o = 16; o; o >>= 1) x += __shfl_xor_sync(0xffffffffu, x, o);
    v[c] = x;
  }
  if (lane == 0) {
    #pragma unroll
    for (int c = 0; c < 7; c++) red[wid * 8 + c] = v[c];
  }
  // f: sum g_fj rows
  {
    const int cchunk = tid & 7, sg = tid >> 3;
    float4 acc[4];
    #pragma unroll
    for (int u = 0; u < 4; u++) acc[u] = make_float4(0.f, 0.f, 0.f, 0.f);
    #pragma unroll
    for (int s4 = 0; s4 < 4; s4++) {
      const int slot = sg * 4 + s4;
      const float4* qp = (const float4*)&g_fj[(gs * 128 + slot) * 128 + cchunk * 16];
      #pragma unroll
      for (int u = 0; u < 4; u++) {
        float4 w = __ldg(&qp[u]);
        acc[u].x += w.x; acc[u].y += w.y; acc[u].z += w.z; acc[u].w += w.w;
      }
    }
    #pragma unroll
    for (int u = 0; u < 4; u++) ((float4*)P)[tid * 4 + u] = acc[u];
  }
  __syncthreads();
  if (tid < 7) {
    float s = 0.f;
    #pragma unroll
    for (int w = 0; w < 8; w++) s += red[w * 8 + tid];
    tot[tid] = s + g_si[gs * 8 + tid];
  }
  if (tid < 128) {
    const int cc = tid >> 4, off = tid & 15;
    float s = 0.f;
    #pragma unroll 8
    for (int sg2 = 0; sg2 < 32; sg2++) s += P[(sg2 * 8 + cc) * 16 + off];
    HT[tid] = s + g_hi[gs * 128 + tid];
  }
  __syncthreads();
  if (tid < 32) {
    float a = 0.f;
    #pragma unroll 8
    for (int h = 0; h < 128; h++) a = fmaf(HT[h], fW2[h * 32 + tid], a);
    out[b * SD + 768 + site * 32 + tid] = a * (1.f / (float)NK) + fb2[tid];
  }
  if (tid == 0) {
    const float inv = 1.f / (float)NK;
    float v1x = tot[0] * inv, v1y = tot[1] * inv, v1z = tot[2] * inv;
    float m2x = tot[3] * inv, m2y = tot[4] * inv, m2z = tot[5] * inv;
    g_vx[gs * 3 + 0] = v1x + (m2y * v1z - m2z * v1y);
    g_vx[gs * 3 + 1] = v1y + (m2z * v1x - m2x * v1z);
    g_vx[gs * 3 + 2] = v1z + (m2x * v1y - m2y * v1x);
    g_tr[gs] = tot[6];
  }
}

// ================= kernel D: batch mean removal + trace =================
__global__ __launch_bounds__(256) void fd_final(float* __restrict__ out)
{
  __shared__ float red[8][4];
  __shared__ float tot[4];
  const int b = blockIdx.x, tid = threadIdx.x;
  const float v0 = g_vx[(b * NPTS + tid) * 3 + 0];
  const float v1 = g_vx[(b * NPTS + tid) * 3 + 1];
  const float v2 = g_vx[(b * NPTS + tid) * 3 + 2];
  const float v3 = g_tr[b * NPTS + tid];
  float r0 = v0, r1 = v1, r2 = v2, r3 = v3;
  #pragma unroll
  for (int o = 16; o; o >>= 1) {
    r0 += __shfl_xor_sync(0xffffffffu, r0, o);
    r1 += __shfl_xor_sync(0xffffffffu, r1, o);
    r2 += __shfl_xor_sync(0xffffffffu, r2, o);
    r3 += __shfl_xor_sync(0xffffffffu, r3, o);
  }
  const int wid = tid >> 5, lane = tid & 31;
  if (lane == 0) { red[wid][0] = r0; red[wid][1] = r1; red[wid][2] = r2; red[wid][3] = r3; }
  __syncthreads();
  if (tid < 4) {
    float s = 0.f;
    #pragma unroll
    for (int w = 0; w < 8; w++) s += red[w][tid];
    tot[tid] = s;
  }
  __syncthreads();
  const float invn = 1.f / (float)NPTS;
  out[b * SD + tid * 3 + 0] = v0 - tot[0] * invn;
  out[b * SD + tid * 3 + 1] = v1 - tot[1] * invn;
  out[b * SD + tid * 3 + 2] = v2 - tot[2] * invn;
  if (tid == 0) out[NBATCH * SD + b] = tot[3] * (1.f / (float)NK);
}

extern "C" void kernel_launch(void* const* d_in, const int* in_sizes, int n_in,
                              void* d_out, int out_size)
{
  const float* state = (const float*)d_in[1];
  const float* mus   = (const float*)d_in[2];
  const float* gam   = (const float*)d_in[3];
  const float* s1W1  = (const float*)d_in[4];
  const float* s1b1  = (const float*)d_in[5];
  const float* s1W2  = (const float*)d_in[6];
  const float* s1b2  = (const float*)d_in[7];
  const float* s2W1  = (const float*)d_in[8];
  const float* s2b1  = (const float*)d_in[9];
  const float* s2W2  = (const float*)d_in[10];
  const float* s2b2  = (const float*)d_in[11];
  const float* fW1   = (const float*)d_in[12];
  const float* fb1   = (const float*)d_in[13];
  const float* fW2   = (const float*)d_in[14];
  const float* fb2   = (const float*)d_in[15];
  float* out = (float*)d_out;

  const int smem_b = SMEM_B * (int)sizeof(float);
  cudaFuncSetAttribute(fd_pairs, cudaFuncAttributeMaxDynamicSharedMemorySize, smem_b);

  fd_prep<<<NSITES, 128>>>(state, s1W1, s1b1, s2W1, s2b1, fW1, fb1);
  fd_pairs<<<NBATCH * 128, 128, smem_b>>>(state, mus, gam,
                                          s1W1, s1W2, s1b2,
                                          s2W1, s2W2, s2b2, fW1);
  fd_comb<<<NSITES, 256>>>(fW2, fb2, out);
  fd_final<<<NBATCH, 256>>>(out);
}

// round 16
// speedup vs baseline: 1.9912x; 1.0330x over previous
#include <cuda_runtime.h>
#include <cuda_fp16.h>
#include <math.h>

#define NBATCH 8
#define NPTS 256
#define NRBF_ 50
#define NK 255
#define SD 8960
#define NSITES 2048

// ---- device scratch (static, allowed) ----
__device__ float  g_c[NSITES * 128 * 4];     // per-site {c1,c2,cf,0} per h
__device__ float  g_sj[NSITES * 128 * 8];    // j-side 7 scalars per (site,slot)
__device__ __half g_fj[NSITES * 128 * 128];  // j-side silu(zf) per (site,slot,h)  fp16
__device__ float  g_si[NSITES * 8];          // i-side reduced 7 per site
__device__ float  g_hi[NSITES * 128];        // i-side f hidden sums per site
__device__ float  g_vx[NSITES * 3];
__device__ float  g_tr[NSITES];

typedef unsigned long long u64;

__device__ __forceinline__ u64 pack2(float x, float y) {
  u64 r; asm("mov.b64 %0,{%1,%2};" : "=l"(r) : "f"(x), "f"(y)); return r;
}
__device__ __forceinline__ float2 unpack2(u64 v) {
  float2 f; asm("mov.b64 {%0,%1},%2;" : "=f"(f.x), "=f"(f.y) : "l"(v)); return f;
}
__device__ __forceinline__ u64 ffma2(u64 a, u64 b, u64 c) {
  u64 d; asm("fma.rn.f32x2 %0,%1,%2,%3;" : "=l"(d) : "l"(a), "l"(b), "l"(c)); return d;
}
__device__ __forceinline__ float sgm(float z) {
  float t; asm("tanh.approx.f32 %0, %1;" : "=f"(t) : "f"(0.5f * z));
  return fmaf(0.5f, t, 0.5f);
}

// ================= kernel A: per-site constants =================
__global__ __launch_bounds__(128) void fd_prep(
    const float* __restrict__ state,
    const float* __restrict__ s1W1, const float* __restrict__ s1b1,
    const float* __restrict__ s2W1, const float* __restrict__ s2b1,
    const float* __restrict__ fW1, const float* __restrict__ fb1)
{
  const int gs = blockIdx.x, b = gs >> 8, site = gs & 255;
  const int h = threadIdx.x;
  __shared__ float fs[32], smx[32];
  if (h < 32) fs[h] = state[b * SD + 768 + site * 32 + h];
  __syncthreads();
  if (h < 32) {
    float v = fs[h], mx = v;
    #pragma unroll
    for (int o = 16; o; o >>= 1) mx = fmaxf(mx, __shfl_xor_sync(0xffffffffu, mx, o));
    float e = __expf(v - mx), s = e;
    #pragma unroll
    for (int o = 16; o; o >>= 1) s += __shfl_xor_sync(0xffffffffu, s, o);
    smx[h] = __fdividef(e, s);
  }
  __syncthreads();
  float c1 = s1b1[h], c2 = s2b1[h], cf = fb1[h];
  #pragma unroll 4
  for (int f = 0; f < 32; f++) {
    float fv = fs[f];
    c1 = fmaf(fv, s1W1[(50 + f) * 128 + h] + s1W1[(82 + f) * 128 + h], c1);
    c2 = fmaf(fv, s2W1[(50 + f) * 128 + h] + s2W1[(82 + f) * 128 + h], c2);
    cf = fmaf(smx[f], fW1[(50 + f) * 128 + h], cf);
  }
  ((float4*)g_c)[gs * 128 + h] = make_float4(c1, c2, cf, 0.f);
}

// ================= kernel B: pair blocks =================
#define O_W1 0
#define O_WM 6400
#define O_W2 12800
#define O_WF 19200
#define O_CS 25600   // float4[256]: [h]=site s0, [128+h]=site s1
#define O_V  26624   // float2[128] {s1W2, s2W2}
#define O_MUS 26880  // 64
#define O_HS 26944   // [4 warps][2 sites][128]
#define O_RED 27968  // 4*16
#define SMEM_B 28032 // floats = 112128 B

__global__ __launch_bounds__(128, 2) void fd_pairs(
    const float* __restrict__ state, const float* __restrict__ mus,
    const float* __restrict__ gamma_p,
    const float* __restrict__ s1W1, const float* __restrict__ s1W2,
    const float* __restrict__ s1b2,
    const float* __restrict__ s2W1, const float* __restrict__ s2W2,
    const float* __restrict__ s2b2,
    const float* __restrict__ fW1)
{
  extern __shared__ float smf[];
  const int tid = threadIdx.x;
  const int wid = tid >> 5, lane = tid & 31;
  const int q = blockIdx.x & 127, b = blockIdx.x >> 7;
  const int s0 = 2 * q, s1 = 2 * q + 1;
  const float gam = gamma_p[0];

  for (int idx = tid; idx < 6400; idx += 128) {
    float w = s1W1[idx];
    smf[O_W1 + idx] = w;
    smf[O_WM + idx] = w * mus[idx >> 7];
    smf[O_W2 + idx] = s2W1[idx];
    smf[O_WF + idx] = fW1[idx];
  }
  for (int idx = tid; idx < 256; idx += 128) {
    int site = (idx < 128) ? s0 : s1;
    ((float4*)&smf[O_CS])[idx] = ((const float4*)g_c)[(b * 256 + site) * 128 + (idx & 127)];
  }
  ((float2*)&smf[O_V])[tid] = make_float2(s1W2[tid], s2W2[tid]);
  if (tid < 64) smf[O_MUS + tid] = (tid < NRBF_) ? mus[tid] : 0.f;
  for (int idx = tid; idx < 1024; idx += 128) smf[O_HS + idx] = 0.f;
  __syncthreads();

  // pair assignment: offset delta = tid+1 (1..128)
  const int dlt = tid + 1;
  const int j0 = (s0 + dlt) & 255;
  const int j1 = (s1 + dlt) & 255;
  const float act0 = (dlt < 128 || s0 < 128) ? 1.f : 0.f;
  const float act1 = (dlt < 128 || s1 < 128) ? 1.f : 0.f;
  const int slot = 127 - tid;
  const int bj0 = b * 256 + j0, bj1 = b * 256 + j1;
  const int gs0 = b * 256 + s0, gs1 = b * 256 + s1;

  const float* xs = state + b * SD;
  const float r0x = xs[s0 * 3 + 0] - xs[j0 * 3 + 0];
  const float r0y = xs[s0 * 3 + 1] - xs[j0 * 3 + 1];
  const float r0z = xs[s0 * 3 + 2] - xs[j0 * 3 + 2];
  const float r1x = xs[s1 * 3 + 0] - xs[j1 * 3 + 0];
  const float r1y = xs[s1 * 3 + 1] - xs[j1 * 3 + 1];
  const float r1z = xs[s1 * 3 + 2] - xs[j1 * 3 + 2];
  const float rr0 = r0x * r0x + r0y * r0y + r0z * r0z;
  const float rr1 = r1x * r1x + r1y * r1y + r1z * r1z;
  const float d0 = sqrtf(rr0 + 1e-6f);
  const float d1 = sqrtf(rr1 + 1e-6f);

  float rb0[NRBF_], rb1[NRBF_];
  #pragma unroll
  for (int m = 0; m < NRBF_; m++) {
    float mu = smf[O_MUS + m];
    float t0 = d0 - mu, t1 = d1 - mu;
    rb0[m] = __expf(-gam * t0 * t0);
    rb1[m] = __expf(-gam * t1 * t1);
  }

  float s1i0 = 0.f, s2i0 = 0.f, dai0 = 0.f, s1i1 = 0.f, s2i1 = 0.f, dai1 = 0.f;
  float s1j0 = 0.f, s2j0 = 0.f, daj0 = 0.f, s1j1 = 0.f, s2j1 = 0.f, daj1 = 0.f;

  #pragma unroll 1
  for (int hb = 0; hb < 128; hb += 4) {
    // prefetch j-side constants (L2) so the m-loop hides their latency
    float4 cj0p[4], cj1p[4];
    #pragma unroll
    for (int e = 0; e < 4; e++) {
      cj0p[e] = __ldg(&((const float4*)g_c)[bj0 * 128 + hb + e]);
      cj1p[e] = __ldg(&((const float4*)g_c)[bj1 * 128 + hb + e]);
    }
    u64 A1a0 = 0, A1b0 = 0, A1a1 = 0, A1b1 = 0;
    u64 AMa0 = 0, AMb0 = 0, AMa1 = 0, AMb1 = 0;
    u64 A2a0 = 0, A2b0 = 0, A2a1 = 0, A2b1 = 0;
    u64 AFa0 = 0, AFb0 = 0, AFa1 = 0, AFb1 = 0;
    #pragma unroll
    for (int m = 0; m < NRBF_; m++) {
      const u64 rv0 = pack2(rb0[m], rb0[m]);
      const u64 rv1 = pack2(rb1[m], rb1[m]);
      const ulonglong2 w1 = *reinterpret_cast<const ulonglong2*>(&smf[O_W1 + m * 128 + hb]);
      A1a0 = ffma2(rv0, w1.x, A1a0);  A1b0 = ffma2(rv0, w1.y, A1b0);
      A1a1 = ffma2(rv1, w1.x, A1a1);  A1b1 = ffma2(rv1, w1.y, A1b1);
      const ulonglong2 wm = *reinterpret_cast<const ulonglong2*>(&smf[O_WM + m * 128 + hb]);
      AMa0 = ffma2(rv0, wm.x, AMa0);  AMb0 = ffma2(rv0, wm.y, AMb0);
      AMa1 = ffma2(rv1, wm.x, AMa1);  AMb1 = ffma2(rv1, wm.y, AMb1);
      const ulonglong2 w2 = *reinterpret_cast<const ulonglong2*>(&smf[O_W2 + m * 128 + hb]);
      A2a0 = ffma2(rv0, w2.x, A2a0);  A2b0 = ffma2(rv0, w2.y, A2b0);
      A2a1 = ffma2(rv1, w2.x, A2a1);  A2b1 = ffma2(rv1, w2.y, A2b1);
      const ulonglong2 wf = *reinterpret_cast<const ulonglong2*>(&smf[O_WF + m * 128 + hb]);
      AFa0 = ffma2(rv0, wf.x, AFa0);  AFb0 = ffma2(rv0, wf.y, AFb0);
      AFa1 = ffma2(rv1, wf.x, AFa1);  AFb1 = ffma2(rv1, wf.y, AFb1);
    }
    float A1[2][4], AM[2][4], A2[2][4], AF[2][4];
    { float2 v;
      v = unpack2(A1a0); A1[0][0] = v.x; A1[0][1] = v.y;
      v = unpack2(A1b0); A1[0][2] = v.x; A1[0][3] = v.y;
      v = unpack2(A1a1); A1[1][0] = v.x; A1[1][1] = v.y;
      v = unpack2(A1b1); A1[1][2] = v.x; A1[1][3] = v.y;
      v = unpack2(AMa0); AM[0][0] = v.x; AM[0][1] = v.y;
      v = unpack2(AMb0); AM[0][2] = v.x; AM[0][3] = v.y;
      v = unpack2(AMa1); AM[1][0] = v.x; AM[1][1] = v.y;
      v = unpack2(AMb1); AM[1][2] = v.x; AM[1][3] = v.y;
      v = unpack2(A2a0); A2[0][0] = v.x; A2[0][1] = v.y;
      v = unpack2(A2b0); A2[0][2] = v.x; A2[0][3] = v.y;
      v = unpack2(A2a1); A2[1][0] = v.x; A2[1][1] = v.y;
      v = unpack2(A2b1); A2[1][2] = v.x; A2[1][3] = v.y;
      v = unpack2(AFa0); AF[0][0] = v.x; AF[0][1] = v.y;
      v = unpack2(AFb0); AF[0][2] = v.x; AF[0][3] = v.y;
      v = unpack2(AFa1); AF[1][0] = v.x; AF[1][1] = v.y;
      v = unpack2(AFb1); AF[1][2] = v.x; AF[1][3] = v.y;
    }
    float fj0[4], fj1[4], si0[4], si1[4];
    #pragma unroll
    for (int e = 0; e < 4; e++) {
      const int h = hb + e;
      const float4 cs0 = ((const float4*)&smf[O_CS])[h];
      const float4 cs1 = ((const float4*)&smf[O_CS])[128 + h];
      const float2 wv = ((const float2*)&smf[O_V])[h];
      const float4 cj0 = cj0p[e];
      const float4 cj1 = cj1p[e];
      { float z = A1[0][e] + cs0.x; float sg = sgm(z);
        s1i0 = fmaf(z * sg, wv.x, s1i0);
        float sp = sg * fmaf(z, 1.f - sg, 1.f);
        dai0 = fmaf(wv.x * sp, fmaf(d0, A1[0][e], -AM[0][e]), dai0);
        float z2 = A2[0][e] + cs0.y;
        s2i0 = fmaf(z2 * sgm(z2), wv.y, s2i0);
        float zf = AF[0][e] + cs0.z; si0[e] = zf * sgm(zf); }
      { float z = A1[0][e] + cj0.x; float sg = sgm(z);
        s1j0 = fmaf(z * sg, wv.x, s1j0);
        float sp = sg * fmaf(z, 1.f - sg, 1.f);
        daj0 = fmaf(wv.x * sp, fmaf(d0, A1[0][e], -AM[0][e]), daj0);
        float z2 = A2[0][e] + cj0.y;
        s2j0 = fmaf(z2 * sgm(z2), wv.y, s2j0);
        float zf = AF[0][e] + cj0.z; fj0[e] = zf * sgm(zf) * act0; }
      { float z = A1[1][e] + cs1.x; float sg = sgm(z);
        s1i1 = fmaf(z * sg, wv.x, s1i1);
        float sp = sg * fmaf(z, 1.f - sg, 1.f);
        dai1 = fmaf(wv.x * sp, fmaf(d1, A1[1][e], -AM[1][e]), dai1);
        float z2 = A2[1][e] + cs1.y;
        s2i1 = fmaf(z2 * sgm(z2), wv.y, s2i1);
        float zf = AF[1][e] + cs1.z; si1[e] = zf * sgm(zf); }
      { float z = A1[1][e] + cj1.x; float sg = sgm(z);
        s1j1 = fmaf(z * sg, wv.x, s1j1);
        float sp = sg * fmaf(z, 1.f - sg, 1.f);
        daj1 = fmaf(wv.x * sp, fmaf(d1, A1[1][e], -AM[1][e]), daj1);
        float z2 = A2[1][e] + cj1.y;
        s2j1 = fmaf(z2 * sgm(z2), wv.y, s2j1);
        float zf = AF[1][e] + cj1.z; fj1[e] = zf * sgm(zf) * act1; }
    }
    // stage j-side f contributions as fp16 (unique rows, 8B aligned)
    {
      __half2 lo0 = __floats2half2_rn(fj0[0], fj0[1]);
      __half2 hi0 = __floats2half2_rn(fj0[2], fj0[3]);
      __half2 lo1 = __floats2half2_rn(fj1[0], fj1[1]);
      __half2 hi1 = __floats2half2_rn(fj1[2], fj1[3]);
      *(__half2*)&g_fj[(bj0 * 128 + slot) * 128 + hb]     = lo0;
      *(__half2*)&g_fj[(bj0 * 128 + slot) * 128 + hb + 2] = hi0;
      *(__half2*)&g_fj[(bj1 * 128 + slot) * 128 + hb]     = lo1;
      *(__half2*)&g_fj[(bj1 * 128 + slot) * 128 + hb + 2] = hi1;
    }
    // i-side f hidden sums (per-warp rows, deterministic)
    #pragma unroll
    for (int e = 0; e < 4; e++) {
      float v0 = si0[e] * act0, v1 = si1[e] * act1;
      #pragma unroll
      for (int o = 16; o; o >>= 1) {
        v0 += __shfl_xor_sync(0xffffffffu, v0, o);
        v1 += __shfl_xor_sync(0xffffffffu, v1, o);
      }
      if (lane == 0) {
        smf[O_HS + (wid * 2 + 0) * 128 + hb + e] += v0;
        smf[O_HS + (wid * 2 + 1) * 128 + hb + e] += v1;
      }
    }
  }

  const float b21 = s1b2[0], b22 = s2b2[0];
  const float s1v0 = (s1i0 + b21) * act0, s2v0 = (s2i0 + b22) * act0;
  const float gd0 = -2.f * gam * dai0 * __fdividef(rr0, d0) * act0;
  const float s1v1 = (s1i1 + b21) * act1, s2v1 = (s2i1 + b22) * act1;
  const float gd1 = -2.f * gam * dai1 * __fdividef(rr1, d1) * act1;
  float vals[14];
  vals[0] = s1v0 * r0x; vals[1] = s1v0 * r0y; vals[2] = s1v0 * r0z;
  vals[3] = s2v0 * r0x; vals[4] = s2v0 * r0y; vals[5] = s2v0 * r0z;
  vals[6] = gd0 + 3.f * s1v0;
  vals[7] = s1v1 * r1x; vals[8] = s1v1 * r1y; vals[9] = s1v1 * r1z;
  vals[10] = s2v1 * r1x; vals[11] = s2v1 * r1y; vals[12] = s2v1 * r1z;
  vals[13] = gd1 + 3.f * s1v1;
  #pragma unroll
  for (int c = 0; c < 14; c++) {
    float v = vals[c];
    #pragma unroll
    for (int o = 16; o; o >>= 1) v += __shfl_xor_sync(0xffffffffu, v, o);
    vals[c] = v;
  }
  if (lane == 0) {
    #pragma unroll
    for (int c = 0; c < 14; c++) smf[O_RED + wid * 16 + c] = vals[c];
  }
  // j-side scalar staging (r_ji = -r_ij)
  {
    const float s1w = (s1j0 + b21) * act0, s2w = (s2j0 + b22) * act0;
    const float gdw = -2.f * gam * daj0 * __fdividef(rr0, d0) * act0;
    float4* o = (float4*)&g_sj[(bj0 * 128 + slot) * 8];
    o[0] = make_float4(-s1w * r0x, -s1w * r0y, -s1w * r0z, -s2w * r0x);
    o[1] = make_float4(-s2w * r0y, -s2w * r0z, gdw + 3.f * s1w, 0.f);
  }
  {
    const float s1w = (s1j1 + b21) * act1, s2w = (s2j1 + b22) * act1;
    const float gdw = -2.f * gam * daj1 * __fdividef(rr1, d1) * act1;
    float4* o = (float4*)&g_sj[(bj1 * 128 + slot) * 8];
    o[0] = make_float4(-s1w * r1x, -s1w * r1y, -s1w * r1z, -s2w * r1x);
    o[1] = make_float4(-s2w * r1y, -s2w * r1z, gdw + 3.f * s1w, 0.f);
  }
  __syncthreads();
  if (tid < 14) {
    float s = 0.f;
    #pragma unroll
    for (int w = 0; w < 4; w++) s += smf[O_RED + w * 16 + tid];
    if (tid < 7) g_si[gs0 * 8 + tid] = s;
    else g_si[gs1 * 8 + tid - 7] = s;
  }
  {
    float h0 = 0.f, h1 = 0.f;
    #pragma unroll
    for (int w = 0; w < 4; w++) {
      h0 += smf[O_HS + (w * 2 + 0) * 128 + tid];
      h1 += smf[O_HS + (w * 2 + 1) * 128 + tid];
    }
    g_hi[gs0 * 128 + tid] = h0;
    g_hi[gs1 * 128 + tid] = h1;
  }
}

// ================= kernel C: per-site combine (coalesced) =================
__global__ __launch_bounds__(128) void fd_comb(
    const float* __restrict__ fW2, const float* __restrict__ fb2,
    float* __restrict__ out)
{
  const int gs = blockIdx.x, b = gs >> 8, site = gs & 255;
  const int tid = threadIdx.x, wid = tid >> 5, lane = tid & 31;
  __shared__ float HT[128];
  __shared__ float red[4 * 8];
  __shared__ float tot[8];

  // f: thread tid = hidden lane h; sum fp16 staging over all 128 slots (coalesced rows)
  {
    float s = 0.f;
    const __half* base = &g_fj[(size_t)gs * 16384 + tid];
    #pragma unroll 8
    for (int slot = 0; slot < 128; slot++) s += __half2float(__ldg(&base[slot * 128]));
    HT[tid] = s + g_hi[gs * 128 + tid];
  }
  // 7 j-side scalars summed over slots (thread = slot)
  float v[7];
  {
    const float4* p = (const float4*)&g_sj[((size_t)gs * 128 + tid) * 8];
    float4 a = __ldg(&p[0]), bb = __ldg(&p[1]);
    v[0] = a.x; v[1] = a.y; v[2] = a.z; v[3] = a.w;
    v[4] = bb.x; v[5] = bb.y; v[6] = bb.z;
  }
  #pragma unroll
  for (int c = 0; c < 7; c++) {
    float x = v[c];
    #pragma unroll
    for (int o = 16; o; o >>= 1) x += __shfl_xor_sync(0xffffffffu, x, o);
    v[c] = x;
  }
  if (lane == 0) {
    #pragma unroll
    for (int c = 0; c < 7; c++) red[wid * 8 + c] = v[c];
  }
  __syncthreads();
  if (tid < 7) {
    float s = 0.f;
    #pragma unroll
    for (int w = 0; w < 4; w++) s += red[w * 8 + tid];
    tot[tid] = s + g_si[gs * 8 + tid];
  }
  __syncthreads();
  if (tid < 32) {
    float a = 0.f;
    #pragma unroll 8
    for (int h = 0; h < 128; h++) a = fmaf(HT[h], fW2[h * 32 + tid], a);
    out[b * SD + 768 + site * 32 + tid] = a * (1.f / (float)NK) + fb2[tid];
  }
  if (tid == 0) {
    const float inv = 1.f / (float)NK;
    float v1x = tot[0] * inv, v1y = tot[1] * inv, v1z = tot[2] * inv;
    float m2x = tot[3] * inv, m2y = tot[4] * inv, m2z = tot[5] * inv;
    g_vx[gs * 3 + 0] = v1x + (m2y * v1z - m2z * v1y);
    g_vx[gs * 3 + 1] = v1y + (m2z * v1x - m2x * v1z);
    g_vx[gs * 3 + 2] = v1z + (m2x * v1y - m2y * v1x);
    g_tr[gs] = tot[6];
  }
}

// ================= kernel D: batch mean removal + trace =================
__global__ __launch_bounds__(256) void fd_final(float* __restrict__ out)
{
  __shared__ float red[8][4];
  __shared__ float tot[4];
  const int b = blockIdx.x, tid = threadIdx.x;
  const float v0 = g_vx[(b * NPTS + tid) * 3 + 0];
  const float v1 = g_vx[(b * NPTS + tid) * 3 + 1];
  const float v2 = g_vx[(b * NPTS + tid) * 3 + 2];
  const float v3 = g_tr[b * NPTS + tid];
  float r0 = v0, r1 = v1, r2 = v2, r3 = v3;
  #pragma unroll
  for (int o = 16; o; o >>= 1) {
    r0 += __shfl_xor_sync(0xffffffffu, r0, o);
    r1 += __shfl_xor_sync(0xffffffffu, r1, o);
    r2 += __shfl_xor_sync(0xffffffffu, r2, o);
    r3 += __shfl_xor_sync(0xffffffffu, r3, o);
  }
  const int wid = tid >> 5, lane = tid & 31;
  if (lane == 0) { red[wid][0] = r0; red[wid][1] = r1; red[wid][2] = r2; red[wid][3] = r3; }
  __syncthreads();
  if (tid < 4) {
    float s = 0.f;
    #pragma unroll
    for (int w = 0; w < 8; w++) s += red[w][tid];
    tot[tid] = s;
  }
  __syncthreads();
  const float invn = 1.f / (float)NPTS;
  out[b * SD + tid * 3 + 0] = v0 - tot[0] * invn;
  out[b * SD + tid * 3 + 1] = v1 - tot[1] * invn;
  out[b * SD + tid * 3 + 2] = v2 - tot[2] * invn;
  if (tid == 0) out[NBATCH * SD + b] = tot[3] * (1.f / (float)NK);
}

extern "C" void kernel_launch(void* const* d_in, const int* in_sizes, int n_in,
                              void* d_out, int out_size)
{
  const float* state = (const float*)d_in[1];
  const float* mus   = (const float*)d_in[2];
  const float* gam   = (const float*)d_in[3];
  const float* s1W1  = (const float*)d_in[4];
  const float* s1b1  = (const float*)d_in[5];
  const float* s1W2  = (const float*)d_in[6];
  const float* s1b2  = (const float*)d_in[7];
  const float* s2W1  = (const float*)d_in[8];
  const float* s2b1  = (const float*)d_in[9];
  const float* s2W2  = (const float*)d_in[10];
  const float* s2b2  = (const float*)d_in[11];
  const float* fW1   = (const float*)d_in[12];
  const float* fb1   = (const float*)d_in[13];
  const float* fW2   = (const float*)d_in[14];
  const float* fb2   = (const float*)d_in[15];
  float* out = (float*)d_out;

  const int smem_b = SMEM_B * (int)sizeof(float);
  cudaFuncSetAttribute(fd_pairs, cudaFuncAttributeMaxDynamicSharedMemorySize, smem_b);

  fd_prep<<<NSITES, 128>>>(state, s1W1, s1b1, s2W1, s2b1, fW1, fb1);
  fd_pairs<<<NBATCH * 128, 128, smem_b>>>(state, mus, gam,
                                          s1W1, s1W2, s1b2,
                                          s2W1, s2W2, s2b2, fW1);
  fd_comb<<<NSITES, 128>>>(fW2, fb2, out);
  fd_final<<<NBATCH, 256>>>(out);
}